// round 1
// baseline (speedup 1.0000x reference)
#include <cuda_runtime.h>

#define BB 4
#define TT 2048
#define SS 2048
#define CC 1024
#define HH 16
#define DD 64
#define SCALE_F 0.125f

typedef unsigned long long u64;

__device__ __forceinline__ u64 pack2(float lo, float hi) {
    u64 r; asm("mov.b64 %0,{%1,%2};" : "=l"(r) : "f"(lo), "f"(hi)); return r;
}
__device__ __forceinline__ void unpack2(u64 v, float& lo, float& hi) {
    asm("mov.b64 {%0,%1},%2;" : "=f"(lo), "=f"(hi) : "l"(v));
}
__device__ __forceinline__ u64 ffma2(u64 a, u64 b, u64 c) {
    u64 d; asm("fma.rn.f32x2 %0,%1,%2,%3;" : "=l"(d) : "l"(a), "l"(b), "l"(c)); return d;
}
__device__ __forceinline__ u64 fmul2(u64 a, u64 b) {
    u64 d; asm("mul.rn.f32x2 %0,%1,%2;" : "=l"(d) : "l"(a), "l"(b)); return d;
}

// Scratch (allocation-free rule: __device__ globals)
__device__ float g_q[BB * HH * TT * DD];     // (B,H,T,D)
__device__ float g_k[BB * HH * SS * DD];     // (B,H,S,D)
__device__ float g_v[BB * HH * SS * DD];     // (B,H,S,D)
__device__ float g_attn[BB * TT * CC];       // (B,T,H*D)

// ---------------------------------------------------------------------------
// GEMM: out = A[M,K] @ W[N,K]^T + bias.
// MODE 0: out row-major (M,N).  MODE 1: scatter to (B,H,T,D) with m=b*T+t, n=h*D+d.
// 128x128 block tile, TK=16, 256 threads, 8x8 per thread, f32x2-packed FMAs.
// ---------------------------------------------------------------------------
template <int MODE>
__global__ __launch_bounds__(256) void gemm_kernel(
    const float* __restrict__ A, const float* __restrict__ W,
    const float* __restrict__ bias, float* __restrict__ out,
    int M, int N, int K)
{
    constexpr int TM = 128, TN = 128, TK = 16;
    __shared__ __align__(16) float As[TK][TM + 4];
    __shared__ __align__(16) float Bs[TK][TN + 4];

    const int tid = threadIdx.x;
    const int tx = tid & 15, ty = tid >> 4;
    const int bm = blockIdx.y * TM, bn = blockIdx.x * TN;

    u64 acc[8][4];
#pragma unroll
    for (int i = 0; i < 8; i++)
#pragma unroll
        for (int j = 0; j < 4; j++) acc[i][j] = 0ull;

    const float* Aptr = A + (size_t)bm * K;
    const float* Wptr = W + (size_t)bn * K;

    for (int k0 = 0; k0 < K; k0 += TK) {
#pragma unroll
        for (int i = 0; i < 2; i++) {
            int c = tid + i * 256;            // 0..511 float4 slots
            int m = c >> 2, kg = (c & 3) << 2;
            float4 va = *(const float4*)(Aptr + (size_t)m * K + k0 + kg);
            As[kg + 0][m] = va.x; As[kg + 1][m] = va.y;
            As[kg + 2][m] = va.z; As[kg + 3][m] = va.w;
            float4 vb = *(const float4*)(Wptr + (size_t)m * K + k0 + kg);
            Bs[kg + 0][m] = vb.x; Bs[kg + 1][m] = vb.y;
            Bs[kg + 2][m] = vb.z; Bs[kg + 3][m] = vb.w;
        }
        __syncthreads();
#pragma unroll
        for (int kk = 0; kk < TK; kk++) {
            float4 a0 = *(const float4*)&As[kk][ty * 8];
            float4 a1 = *(const float4*)&As[kk][ty * 8 + 4];
            const u64* bp = (const u64*)&Bs[kk][tx * 8];
            u64 b0 = bp[0], b1 = bp[1], b2 = bp[2], b3 = bp[3];
            float av[8] = {a0.x, a0.y, a0.z, a0.w, a1.x, a1.y, a1.z, a1.w};
#pragma unroll
            for (int i = 0; i < 8; i++) {
                u64 ab = pack2(av[i], av[i]);
                acc[i][0] = ffma2(ab, b0, acc[i][0]);
                acc[i][1] = ffma2(ab, b1, acc[i][1]);
                acc[i][2] = ffma2(ab, b2, acc[i][2]);
                acc[i][3] = ffma2(ab, b3, acc[i][3]);
            }
        }
        __syncthreads();
    }

#pragma unroll
    for (int i = 0; i < 8; i++) {
        int m = bm + ty * 8 + i;
#pragma unroll
        for (int j = 0; j < 4; j++) {
            float lo, hi;
            unpack2(acc[i][j], lo, hi);
            int n0 = bn + tx * 8 + j * 2;
            float v0 = lo + bias[n0];
            float v1 = hi + bias[n0 + 1];
            if (MODE == 0) {
                float* p = out + (size_t)m * N + n0;
                p[0] = v0; p[1] = v1;
            } else {
                int b_ = m >> 11, t = m & (TT - 1);
                int h = n0 >> 6, d = n0 & (DD - 1);
                float* p = out + (((size_t)b_ * HH + h) * TT + t) * DD + d;
                p[0] = v0; p[1] = v1;
            }
        }
    }
}

// ---------------------------------------------------------------------------
// Flash attention: per (b, h, 128-row T tile), stream S in 64-wide tiles.
// 256 threads as 16x16 grid; thread (tx,ty) owns S rows ty*8..+7.
// Q,K stored d-major in smem (conflict-free); online softmax in registers.
// ---------------------------------------------------------------------------
#define ATTN_SMEM_FLOATS (DD * 132 + DD * 66 + 64 * 68 + 128 * 68 + 64)
#define ATTN_SMEM_BYTES (ATTN_SMEM_FLOATS * 4)

__global__ __launch_bounds__(256) void attn_kernel(
    const float* __restrict__ mask, const unsigned char* __restrict__ kpm)
{
    extern __shared__ __align__(16) float sm[];
    float* Qs = sm;                       // [DD][132]  (d-major, t cols)
    float* Ks = Qs + DD * 132;            // [DD][66]   (d-major, s cols)
    float* Vs = Ks + DD * 66;             // [64][68]   (s rows, d cols)
    float* Ps = Vs + 64 * 68;             // [128][68]  (t rows, s cols)
    float* kpms = Ps + 128 * 68;          // [64]

    const int tid = threadIdx.x;
    const int tx = tid & 15, ty = tid >> 4;
    const int tblk = blockIdx.x * 128;
    const int h = blockIdx.y, b = blockIdx.z;
    const size_t base = ((size_t)b * HH + h) * (size_t)TT * DD;
    const float NEGINF = __int_as_float(0xff800000);

    {   // load Q tile (128 x 64), store transposed
        const float* qp = g_q + base + (size_t)tblk * DD;
#pragma unroll
        for (int i = 0; i < 8; i++) {
            int c = tid + i * 256;          // 0..2047 float4 slots
            int t = c >> 4, dg = (c & 15) << 2;
            float4 v = *(const float4*)(qp + t * DD + dg);
            Qs[(dg + 0) * 132 + t] = v.x;
            Qs[(dg + 1) * 132 + t] = v.y;
            Qs[(dg + 2) * 132 + t] = v.z;
            Qs[(dg + 3) * 132 + t] = v.w;
        }
    }

    float m_i[8], l_i[8];
    u64 o0[8], o1[8];
#pragma unroll
    for (int i = 0; i < 8; i++) { m_i[i] = NEGINF; l_i[i] = 0.f; o0[i] = 0ull; o1[i] = 0ull; }

    for (int s0 = 0; s0 < SS; s0 += 64) {
        const float* kp = g_k + base + (size_t)s0 * DD;
        const float* vp = g_v + base + (size_t)s0 * DD;
#pragma unroll
        for (int i = 0; i < 4; i++) {
            int c = tid + i * 256;          // 0..1023 float4 slots
            int s = c >> 4, dg = (c & 15) << 2;
            float4 kv = *(const float4*)(kp + s * DD + dg);
            Ks[(dg + 0) * 66 + s] = kv.x;
            Ks[(dg + 1) * 66 + s] = kv.y;
            Ks[(dg + 2) * 66 + s] = kv.z;
            Ks[(dg + 3) * 66 + s] = kv.w;
            float4 vv = *(const float4*)(vp + s * DD + dg);
            *(float4*)&Vs[s * 68 + dg] = vv;
        }
        if (tid < 64) kpms[tid] = kpm[(size_t)b * SS + s0 + tid] ? NEGINF : 0.f;
        __syncthreads();

        // S = Q @ K^T : rows ty*8..+7, cols tx*4..+3 (packed pairs)
        u64 sa[8], sb[8];
#pragma unroll
        for (int i = 0; i < 8; i++) { sa[i] = 0ull; sb[i] = 0ull; }
#pragma unroll 8
        for (int d = 0; d < DD; d++) {
            float4 a0 = *(const float4*)&Qs[d * 132 + ty * 8];
            float4 a1 = *(const float4*)&Qs[d * 132 + ty * 8 + 4];
            u64 k0 = *(const u64*)&Ks[d * 66 + tx * 4];
            u64 k1 = *(const u64*)&Ks[d * 66 + tx * 4 + 2];
            float av[8] = {a0.x, a0.y, a0.z, a0.w, a1.x, a1.y, a1.z, a1.w};
#pragma unroll
            for (int i = 0; i < 8; i++) {
                u64 ab = pack2(av[i], av[i]);
                sa[i] = ffma2(ab, k0, sa[i]);
                sb[i] = ffma2(ab, k1, sb[i]);
            }
        }

        // online softmax per row (row reduction over 16 lanes of half-warp)
#pragma unroll
        for (int i = 0; i < 8; i++) {
            int tg = tblk + ty * 8 + i;
            float4 mv = *(const float4*)(mask + (size_t)tg * SS + s0 + tx * 4);
            float s0v, s1v, s2v, s3v;
            unpack2(sa[i], s0v, s1v);
            unpack2(sb[i], s2v, s3v);
            s0v = fmaf(s0v, SCALE_F, mv.x) + kpms[tx * 4 + 0];
            s1v = fmaf(s1v, SCALE_F, mv.y) + kpms[tx * 4 + 1];
            s2v = fmaf(s2v, SCALE_F, mv.z) + kpms[tx * 4 + 2];
            s3v = fmaf(s3v, SCALE_F, mv.w) + kpms[tx * 4 + 3];
            float mx = fmaxf(fmaxf(s0v, s1v), fmaxf(s2v, s3v));
#pragma unroll
            for (int off = 8; off; off >>= 1)
                mx = fmaxf(mx, __shfl_xor_sync(0xffffffffu, mx, off));
            float mnew = fmaxf(m_i[i], mx);
            float corr = __expf(m_i[i] - mnew);
            m_i[i] = mnew;
            float p0 = __expf(s0v - mnew);
            float p1 = __expf(s1v - mnew);
            float p2 = __expf(s2v - mnew);
            float p3 = __expf(s3v - mnew);
            float ps = (p0 + p1) + (p2 + p3);
#pragma unroll
            for (int off = 8; off; off >>= 1)
                ps += __shfl_xor_sync(0xffffffffu, ps, off);
            l_i[i] = l_i[i] * corr + ps;
            u64 c2 = pack2(corr, corr);
            o0[i] = fmul2(o0[i], c2);
            o1[i] = fmul2(o1[i], c2);
            *(float4*)&Ps[(ty * 8 + i) * 68 + tx * 4] = make_float4(p0, p1, p2, p3);
        }
        __syncthreads();

        // O += P @ V : rows ty*8..+7, d cols tx*4..+3 (packed pairs)
#pragma unroll 8
        for (int s = 0; s < 64; s++) {
            u64 v0 = *(const u64*)&Vs[s * 68 + tx * 4];
            u64 v1 = *(const u64*)&Vs[s * 68 + tx * 4 + 2];
#pragma unroll
            for (int i = 0; i < 8; i++) {
                float p = Ps[(ty * 8 + i) * 68 + s];
                u64 pb = pack2(p, p);
                o0[i] = ffma2(pb, v0, o0[i]);
                o1[i] = ffma2(pb, v1, o1[i]);
            }
        }
        __syncthreads();
    }

    // finalize: O /= l, write to (B, T, H*D)
#pragma unroll
    for (int i = 0; i < 8; i++) {
        float inv = __fdividef(1.f, l_i[i]);
        float a, bvv, c, d2;
        unpack2(o0[i], a, bvv);
        unpack2(o1[i], c, d2);
        int t = tblk + ty * 8 + i;
        float* op = g_attn + ((size_t)b * TT + t) * CC + h * DD + tx * 4;
        *(float4*)op = make_float4(a * inv, bvv * inv, c * inv, d2 * inv);
    }
}

// ---------------------------------------------------------------------------
// Launch
// ---------------------------------------------------------------------------
extern "C" void kernel_launch(void* const* d_in, const int* in_sizes, int n_in,
                              void* d_out, int out_size)
{
    (void)in_sizes; (void)n_in; (void)out_size;
    const float* query = (const float*)d_in[0];
    const float* key   = (const float*)d_in[1];
    const float* value = (const float*)d_in[2];
    const float* mask  = (const float*)d_in[3];
    const unsigned char* kpm = (const unsigned char*)d_in[4];
    const float* Wq = (const float*)d_in[5];
    const float* bq = (const float*)d_in[6];
    const float* Wk = (const float*)d_in[7];
    const float* bk = (const float*)d_in[8];
    const float* Wv = (const float*)d_in[9];
    const float* bv = (const float*)d_in[10];
    const float* Wout = (const float*)d_in[11];
    const float* bout = (const float*)d_in[12];
    float* out = (float*)d_out;

    float *qp, *kp, *vp, *ap;
    cudaGetSymbolAddress((void**)&qp, g_q);
    cudaGetSymbolAddress((void**)&kp, g_k);
    cudaGetSymbolAddress((void**)&vp, g_v);
    cudaGetSymbolAddress((void**)&ap, g_attn);

    dim3 ggrid(CC / 128, (BB * TT) / 128);   // (8, 64)
    gemm_kernel<1><<<ggrid, 256>>>(query, Wq, bq, qp, BB * TT, CC, CC);
    gemm_kernel<1><<<ggrid, 256>>>(key,   Wk, bk, kp, BB * SS, CC, CC);
    gemm_kernel<1><<<ggrid, 256>>>(value, Wv, bv, vp, BB * SS, CC, CC);

    cudaFuncSetAttribute(attn_kernel, cudaFuncAttributeMaxDynamicSharedMemorySize,
                         ATTN_SMEM_BYTES);
    attn_kernel<<<dim3(TT / 128, HH, BB), 256, ATTN_SMEM_BYTES>>>(mask, kpm);

    gemm_kernel<0><<<ggrid, 256>>>(ap, Wout, bout, out, BB * TT, CC, CC);
}